// round 1
// baseline (speedup 1.0000x reference)
#include <cuda_runtime.h>
#include <cstdint>

// MMDNE fused kernel for GB300 (sm_103a).
// Phase 1: per-thread embedding GEMM (2 vector-rows/thread) using packed
//          fma.rn.f32x2, W broadcast from SMEM (one read feeds 2 rows).
// Phase 2: in-block epilogue (attention weights + squared-distance scores).

#define BB   50000
#define FF   128
#define EE   32
#define HH   2
#define NNEG 10
#define VV   26              // vector-rows per batch row: s,t,sh0,sh1,th0,th1,sn0..9,tn0..9
#define ROWS 32              // batch rows per block
#define MV   (ROWS * VV)     // 832 vector-rows per block
#define NT   416             // threads per block (each owns 2 vector-rows)
#define ESTR 33              // padded embedding stride (bank-conflict-free)

struct SmemT {
    float W[FF * EE];        // 4096 floats, 16KB, [f][e]
    float bias[EE];
    float avec[2 * EE];      // a_cur = avec[0..31], a_his = avec[32..63]
    float deltas[2];
    float emb[MV * ESTR];    // 27456 floats
    float sq[MV];
    float dots[ROWS * 6];    // s*ac, t*ac, sh0*ah, sh1*ah, th0*ah, th1*ah
    float w[ROWS * 4];       // w_s0, w_s1, w_t0, w_t1
};

__device__ __forceinline__ float2 ffma2(float2 x, float2 w, float2 c) {
#if __CUDA_ARCH__ >= 1000
    unsigned long long xu = *reinterpret_cast<unsigned long long*>(&x);
    unsigned long long wu = *reinterpret_cast<unsigned long long*>(&w);
    unsigned long long cu = *reinterpret_cast<unsigned long long*>(&c);
    unsigned long long du;
    asm("fma.rn.f32x2 %0, %1, %2, %3;" : "=l"(du) : "l"(xu), "l"(wu), "l"(cu));
    return *reinterpret_cast<float2*>(&du);
#else
    return make_float2(fmaf(x.x, w.x, c.x), fmaf(x.y, w.y, c.y));
#endif
}

__device__ __forceinline__ const float* src_ptr(
    int v, int rg,
    const float* s_fts, const float* t_fts,
    const float* s_h, const float* t_h,
    const float* s_n, const float* t_n)
{
    if (v == 0)  return s_fts + (long)rg * FF;
    if (v == 1)  return t_fts + (long)rg * FF;
    if (v < 4)   return s_h + ((long)rg * HH + (v - 2)) * FF;
    if (v < 6)   return t_h + ((long)rg * HH + (v - 4)) * FF;
    if (v < 16)  return s_n + ((long)rg * NNEG + (v - 6)) * FF;
    return t_n + ((long)rg * NNEG + (v - 16)) * FF;
}

__device__ __forceinline__ void step_f(const float* wrow, float xa, float xb,
                                       float2* accA, float2* accB)
{
    float2 xxA = make_float2(xa, xa);
    float2 xxB = make_float2(xb, xb);
    const float4* w4 = reinterpret_cast<const float4*>(wrow);
#pragma unroll
    for (int j = 0; j < 8; ++j) {
        float4 w = w4[j];
        float2 w01 = make_float2(w.x, w.y);
        float2 w23 = make_float2(w.z, w.w);
        accA[2 * j]     = ffma2(xxA, w01, accA[2 * j]);
        accA[2 * j + 1] = ffma2(xxA, w23, accA[2 * j + 1]);
        accB[2 * j]     = ffma2(xxB, w01, accB[2 * j]);
        accB[2 * j + 1] = ffma2(xxB, w23, accB[2 * j + 1]);
    }
}

__global__ void __launch_bounds__(NT, 1) mmdne_kernel(
    const float* __restrict__ s_fts, const float* __restrict__ t_fts,
    const float* __restrict__ s_h_fts, const float* __restrict__ t_h_fts,
    const float* __restrict__ s_neg_fts, const float* __restrict__ t_neg_fts,
    const float* __restrict__ event_time,
    const float* __restrict__ s_h_times, const float* __restrict__ t_h_times,
    const float* __restrict__ s_h_mask, const float* __restrict__ t_h_mask,
    const float* __restrict__ W_fts, const float* __restrict__ b_fts,
    const float* __restrict__ a_vec,
    const float* __restrict__ delta_s, const float* __restrict__ delta_t,
    float* __restrict__ out)
{
    extern __shared__ char smem_raw[];
    SmemT& sm = *reinterpret_cast<SmemT*>(smem_raw);
    const int tid = threadIdx.x;
    const int row_base = blockIdx.x * ROWS;

    // ---- Phase 0: stage W, bias, a, deltas ----
    for (int i = tid; i < FF * EE; i += NT) sm.W[i] = W_fts[i];
    if (tid < EE)      sm.bias[tid] = b_fts[tid];
    if (tid < 2 * EE)  sm.avec[tid] = a_vec[tid];
    if (tid == 0) { sm.deltas[0] = delta_s[0]; sm.deltas[1] = delta_t[0]; }
    __syncthreads();

    // ---- Phase 1: embedding GEMM, 2 vector-rows per thread ----
    const int m0 = 2 * tid;
    const int m1 = m0 + 1;
    const int r0 = m0 / VV, v0 = m0 % VV;
    const int r1 = m1 / VV, v1 = m1 % VV;
    int rgA = row_base + r0; if (rgA >= BB) rgA = BB - 1;
    int rgB = row_base + r1; if (rgB >= BB) rgB = BB - 1;

    const float4* pA = reinterpret_cast<const float4*>(
        src_ptr(v0, rgA, s_fts, t_fts, s_h_fts, t_h_fts, s_neg_fts, t_neg_fts));
    const float4* pB = reinterpret_cast<const float4*>(
        src_ptr(v1, rgB, s_fts, t_fts, s_h_fts, t_h_fts, s_neg_fts, t_neg_fts));

    float2 accA[16], accB[16];
#pragma unroll
    for (int j = 0; j < 16; ++j) {
        float2 bv = make_float2(sm.bias[2 * j], sm.bias[2 * j + 1]);
        accA[j] = bv;
        accB[j] = bv;
    }

    // double-buffered: 8 f per iteration (2 float4 per row)
    float4 nA0 = pA[0], nA1 = pA[1];
    float4 nB0 = pB[0], nB1 = pB[1];
#pragma unroll 1
    for (int c = 0; c < 16; ++c) {
        float4 cA0 = nA0, cA1 = nA1, cB0 = nB0, cB1 = nB1;
        if (c < 15) {
            nA0 = pA[2 * c + 2]; nA1 = pA[2 * c + 3];
            nB0 = pB[2 * c + 2]; nB1 = pB[2 * c + 3];
        }
        const float* wb = sm.W + c * 8 * EE;
        step_f(wb + 0 * EE, cA0.x, cB0.x, accA, accB);
        step_f(wb + 1 * EE, cA0.y, cB0.y, accA, accB);
        step_f(wb + 2 * EE, cA0.z, cB0.z, accA, accB);
        step_f(wb + 3 * EE, cA0.w, cB0.w, accA, accB);
        step_f(wb + 4 * EE, cA1.x, cB1.x, accA, accB);
        step_f(wb + 5 * EE, cA1.y, cB1.y, accA, accB);
        step_f(wb + 6 * EE, cA1.z, cB1.z, accA, accB);
        step_f(wb + 7 * EE, cA1.w, cB1.w, accA, accB);
    }

    // ---- Phase 2a: store embeddings, sqnorms, a-projections (from registers) ----
    {
        float sqA = 0.f, sqB = 0.f;
#pragma unroll
        for (int j = 0; j < 16; ++j) {
            sm.emb[m0 * ESTR + 2 * j]     = accA[j].x;
            sm.emb[m0 * ESTR + 2 * j + 1] = accA[j].y;
            sm.emb[m1 * ESTR + 2 * j]     = accB[j].x;
            sm.emb[m1 * ESTR + 2 * j + 1] = accB[j].y;
            sqA += accA[j].x * accA[j].x + accA[j].y * accA[j].y;
            sqB += accB[j].x * accB[j].x + accB[j].y * accB[j].y;
        }
        sm.sq[m0] = sqA;
        sm.sq[m1] = sqB;
        if (v0 < 6) {
            const float* av = (v0 < 2) ? sm.avec : (sm.avec + EE);
            float d = 0.f;
#pragma unroll
            for (int j = 0; j < 16; ++j)
                d += accA[j].x * av[2 * j] + accA[j].y * av[2 * j + 1];
            sm.dots[r0 * 6 + v0] = d;
        }
        if (v1 < 6) {
            const float* av = (v1 < 2) ? sm.avec : (sm.avec + EE);
            float d = 0.f;
#pragma unroll
            for (int j = 0; j < 16; ++j)
                d += accB[j].x * av[2 * j] + accB[j].y * av[2 * j + 1];
            sm.dots[r1 * 6 + v1] = d;
        }
    }
    __syncthreads();

    // ---- Phase 2b: per-row attention weights (32 threads) ----
    if (tid < ROWS) {
        const int r = tid;
        int rg = row_base + r; if (rg >= BB) rg = BB - 1;
        const float ds = sm.deltas[0];
        const float dt = sm.deltas[1];
        const float et = event_time[rg];

        // s side
        float dts0 = fabsf(et - s_h_times[rg * 2 + 0]);
        float dts1 = fabsf(et - s_h_times[rg * 2 + 1]);
        float sc0 = sm.dots[r * 6 + 0] + sm.dots[r * 6 + 2];
        float sc1 = sm.dots[r * 6 + 0] + sm.dots[r * 6 + 3];
        float sim0 = expf(-ds * dts0) * sc0; sim0 = (sim0 > 0.f) ? sim0 : 0.2f * sim0;
        float sim1 = expf(-ds * dts1) * sc1; sim1 = (sim1 > 0.f) ? sim1 : 0.2f * sim1;
        float mx = fmaxf(sim0, sim1);
        float e0 = expf(sim0 - mx), e1 = expf(sim1 - mx);
        float inv = 1.f / (e0 + e1);
        sm.w[r * 4 + 0] = e0 * inv * expf(ds * dts0) * s_h_mask[rg * 2 + 0];
        sm.w[r * 4 + 1] = e1 * inv * expf(ds * dts1) * s_h_mask[rg * 2 + 1];

        // t side
        float dtt0 = fabsf(et - t_h_times[rg * 2 + 0]);
        float dtt1 = fabsf(et - t_h_times[rg * 2 + 1]);
        float tc0 = sm.dots[r * 6 + 1] + sm.dots[r * 6 + 4];
        float tc1 = sm.dots[r * 6 + 1] + sm.dots[r * 6 + 5];
        float tm0 = expf(-dt * dtt0) * tc0; tm0 = (tm0 > 0.f) ? tm0 : 0.2f * tm0;
        float tm1 = expf(-dt * dtt1) * tc1; tm1 = (tm1 > 0.f) ? tm1 : 0.2f * tm1;
        float mx2 = fmaxf(tm0, tm1);
        float f0 = expf(tm0 - mx2), f1 = expf(tm1 - mx2);
        float inv2 = 1.f / (f0 + f1);
        sm.w[r * 4 + 2] = f0 * inv2 * expf(dt * dtt0) * t_h_mask[rg * 2 + 0];
        sm.w[r * 4 + 3] = f1 * inv2 * expf(dt * dtt1) * t_h_mask[rg * 2 + 1];
    }
    __syncthreads();

    // ---- Phase 2c: 21 outputs per row, 672 items per block ----
    for (int it = tid; it < ROWS * 21; it += NT) {
        const int r = it / 21;
        const int k = it % 21;
        const int rg = row_base + r;
        if (rg >= BB) continue;
        const float* base = sm.emb + r * VV * ESTR;

        if (k == 0) {
            // p_lambda = -||s - t||^2 + sum_h w_s[h] * (-||s_h[h] - t||^2)
            const float* es  = base;
            const float* etb = base + 1 * ESTR;
            const float* h0  = base + 2 * ESTR;
            const float* h1  = base + 3 * ESTR;
            float pm = 0.f, pa0 = 0.f, pa1 = 0.f;
#pragma unroll
            for (int e = 0; e < EE; ++e) {
                float te = etb[e];
                float d0 = es[e] - te; pm  -= d0 * d0;
                float d1 = h0[e] - te; pa0 -= d1 * d1;
                float d2 = h1[e] - te; pa1 -= d2 * d2;
            }
            out[rg] = pm + sm.w[r * 4 + 0] * pa0 + sm.w[r * 4 + 1] * pa1;
        } else if (k <= 10) {
            // n_lambda_s[n]: s vs t_neg[n], history s_h
            const int n = k - 1;
            const float* en = base + (16 + n) * ESTR;
            const float* es = base;
            const float* h0 = base + 2 * ESTR;
            const float* h1 = base + 3 * ESTR;
            float d_s = 0.f, d0 = 0.f, d1 = 0.f;
#pragma unroll
            for (int e = 0; e < EE; ++e) {
                float x = en[e];
                d_s += es[e] * x;
                d0  += h0[e] * x;
                d1  += h1[e] * x;
            }
            float sqn = sm.sq[r * VV + 16 + n];
            float nmu = -(sm.sq[r * VV + 0] + sqn - 2.f * d_s);
            float na0 = -(sm.sq[r * VV + 2] + sqn - 2.f * d0);
            float na1 = -(sm.sq[r * VV + 3] + sqn - 2.f * d1);
            out[BB + (long)rg * NNEG + n] =
                nmu + sm.w[r * 4 + 0] * na0 + sm.w[r * 4 + 1] * na1;
        } else {
            // n_lambda_t[n]: t vs s_neg[n], history t_h
            const int n = k - 11;
            const float* en = base + (6 + n) * ESTR;
            const float* et2 = base + 1 * ESTR;
            const float* h0 = base + 4 * ESTR;
            const float* h1 = base + 5 * ESTR;
            float d_t = 0.f, d0 = 0.f, d1 = 0.f;
#pragma unroll
            for (int e = 0; e < EE; ++e) {
                float x = en[e];
                d_t += et2[e] * x;
                d0  += h0[e] * x;
                d1  += h1[e] * x;
            }
            float sqn = sm.sq[r * VV + 6 + n];
            float nmu = -(sm.sq[r * VV + 1] + sqn - 2.f * d_t);
            float na0 = -(sm.sq[r * VV + 4] + sqn - 2.f * d0);
            float na1 = -(sm.sq[r * VV + 5] + sqn - 2.f * d1);
            out[BB + (long)BB * NNEG + (long)rg * NNEG + n] =
                nmu + sm.w[r * 4 + 2] * na0 + sm.w[r * 4 + 3] * na1;
        }
    }
}

extern "C" void kernel_launch(void* const* d_in, const int* in_sizes, int n_in,
                              void* d_out, int out_size)
{
    const float* s_fts      = (const float*)d_in[0];
    const float* t_fts      = (const float*)d_in[1];
    const float* s_h_fts    = (const float*)d_in[2];
    const float* t_h_fts    = (const float*)d_in[3];
    const float* s_neg_fts  = (const float*)d_in[4];
    const float* t_neg_fts  = (const float*)d_in[5];
    const float* event_time = (const float*)d_in[6];
    const float* s_h_times  = (const float*)d_in[7];
    const float* t_h_times  = (const float*)d_in[8];
    const float* s_h_mask   = (const float*)d_in[9];
    const float* t_h_mask   = (const float*)d_in[10];
    const float* W_fts      = (const float*)d_in[11];
    const float* b_fts      = (const float*)d_in[12];
    const float* a_vec      = (const float*)d_in[13];
    const float* delta_s    = (const float*)d_in[14];
    const float* delta_t    = (const float*)d_in[15];
    float* out = (float*)d_out;

    const int smem_bytes = (int)sizeof(SmemT);
    cudaFuncSetAttribute(mmdne_kernel,
                         cudaFuncAttributeMaxDynamicSharedMemorySize, smem_bytes);

    const int nblocks = (BB + ROWS - 1) / ROWS;  // 1563
    mmdne_kernel<<<nblocks, NT, smem_bytes>>>(
        s_fts, t_fts, s_h_fts, t_h_fts, s_neg_fts, t_neg_fts,
        event_time, s_h_times, t_h_times, s_h_mask, t_h_mask,
        W_fts, b_fts, a_vec, delta_s, delta_t, out);
}

// round 3
// speedup vs baseline: 1.2495x; 1.2495x over previous
#include <cuda_runtime.h>
#include <cstdint>

// MMDNE fused kernel, R3: register-tiled (8x8) embedding GEMM.
// R2 -> R3 fix: the staging/emb union must be 16B aligned for LDS.128
// (struct offset before it was 21384 B == 8 mod 16 -> misaligned address).

#define BB   50000
#define FF   128
#define EE   32
#define HH   2
#define NNEG 10
#define VV   26              // vector-rows per batch row
#define ROWS 32              // batch rows per block
#define MV   (ROWS * VV)     // 832
#define NT   416             // threads (13 warps)
#define ESTR 34              // emb stride (even -> 8B-aligned float2 stores)
#define MVP  836             // xT row stride (mult of 4 for LDS.128 alignment)
#define FC   16              // k-chunk
#define NCHUNK (FF / FC)     // 8

struct SmemT {
    float W[FF * EE];        // [k][e], 16KB
    float bias[EE];
    float avec[2 * EE];
    float deltas[2];
    float sq[MV];
    float dots[ROWS * 6];
    float wts[ROWS * 4];
    alignas(16) union {
        float xT[2][FC * MVP];   // 2*13376 floats (staging, mainloop only)
        float emb[MV * ESTR];    // 28288 floats (epilogue only)
    } u;
};

__device__ __forceinline__ float2 ffma2(float2 x, float2 w, float2 c) {
#if __CUDA_ARCH__ >= 1000
    unsigned long long xu = *reinterpret_cast<unsigned long long*>(&x);
    unsigned long long wu = *reinterpret_cast<unsigned long long*>(&w);
    unsigned long long cu = *reinterpret_cast<unsigned long long*>(&c);
    unsigned long long du;
    asm("fma.rn.f32x2 %0, %1, %2, %3;" : "=l"(du) : "l"(xu), "l"(wu), "l"(cu));
    return *reinterpret_cast<float2*>(&du);
#else
    return make_float2(fmaf(x.x, w.x, c.x), fmaf(x.y, w.y, c.y));
#endif
}

__device__ __forceinline__ const float* src_ptr(
    int v, int rg,
    const float* s_fts, const float* t_fts,
    const float* s_h, const float* t_h,
    const float* s_n, const float* t_n)
{
    if (v == 0)  return s_fts + (long)rg * FF;
    if (v == 1)  return t_fts + (long)rg * FF;
    if (v < 4)   return s_h + ((long)rg * HH + (v - 2)) * FF;
    if (v < 6)   return t_h + ((long)rg * HH + (v - 4)) * FF;
    if (v < 16)  return s_n + ((long)rg * NNEG + (v - 6)) * FF;
    return t_n + ((long)rg * NNEG + (v - 16)) * FF;
}

__global__ void __launch_bounds__(NT, 1) mmdne_kernel(
    const float* __restrict__ s_fts, const float* __restrict__ t_fts,
    const float* __restrict__ s_h_fts, const float* __restrict__ t_h_fts,
    const float* __restrict__ s_neg_fts, const float* __restrict__ t_neg_fts,
    const float* __restrict__ event_time,
    const float* __restrict__ s_h_times, const float* __restrict__ t_h_times,
    const float* __restrict__ s_h_mask, const float* __restrict__ t_h_mask,
    const float* __restrict__ W_fts, const float* __restrict__ b_fts,
    const float* __restrict__ a_vec,
    const float* __restrict__ delta_s, const float* __restrict__ delta_t,
    float* __restrict__ out)
{
    extern __shared__ char smem_raw[];
    SmemT& sm = *reinterpret_cast<SmemT*>(smem_raw);
    const int tid = threadIdx.x;
    const int row_base = blockIdx.x * ROWS;

    // ---- Phase 0: stage W, bias, a, deltas ----
    for (int i = tid; i < FF * EE; i += NT) sm.W[i] = W_fts[i];
    if (tid < EE)      sm.bias[tid] = b_fts[tid];
    if (tid < 2 * EE)  sm.avec[tid] = a_vec[tid];
    if (tid == 0) { sm.deltas[0] = delta_s[0]; sm.deltas[1] = delta_t[0]; }

    const int ngrp = tid & 3;          // 0..3  -> n0 = 8*ngrp
    const int mgrp = tid >> 2;         // 0..103 -> m0 = 8*mgrp
    const int m0 = mgrp * 8;
    const int n0 = ngrp * 8;

    float4 stg[8];

    // ---- stage chunk 0 ----
    {
#pragma unroll
        for (int i = 0; i < 8; ++i) {
            int id = tid + i * NT;            // 0..3327
            int m = id >> 2, q = id & 3;
            int r = m / VV, vv = m - r * VV;
            int rg = row_base + r; if (rg >= BB) rg = BB - 1;
            const float4* p = reinterpret_cast<const float4*>(
                src_ptr(vv, rg, s_fts, t_fts, s_h_fts, t_h_fts, s_neg_fts, t_neg_fts));
            stg[i] = p[q];
        }
        float* b = sm.u.xT[0];
#pragma unroll
        for (int i = 0; i < 8; ++i) {
            int id = tid + i * NT;
            int m = id >> 2, q = id & 3;
            b[(4 * q + 0) * MVP + m] = stg[i].x;
            b[(4 * q + 1) * MVP + m] = stg[i].y;
            b[(4 * q + 2) * MVP + m] = stg[i].z;
            b[(4 * q + 3) * MVP + m] = stg[i].w;
        }
    }
    __syncthreads();

    // ---- acc init from bias ----
    float2 acc[8][4];
    {
        float2 b0 = make_float2(sm.bias[n0 + 0], sm.bias[n0 + 1]);
        float2 b1 = make_float2(sm.bias[n0 + 2], sm.bias[n0 + 3]);
        float2 b2 = make_float2(sm.bias[n0 + 4], sm.bias[n0 + 5]);
        float2 b3 = make_float2(sm.bias[n0 + 6], sm.bias[n0 + 7]);
#pragma unroll
        for (int mi = 0; mi < 8; ++mi) {
            acc[mi][0] = b0; acc[mi][1] = b1; acc[mi][2] = b2; acc[mi][3] = b3;
        }
    }

    // ---- mainloop over k-chunks ----
    for (int kc = 0; kc < NCHUNK; ++kc) {
        if (kc + 1 < NCHUNK) {
            const int k0 = (kc + 1) * FC;
#pragma unroll
            for (int i = 0; i < 8; ++i) {
                int id = tid + i * NT;
                int m = id >> 2, q = id & 3;
                int r = m / VV, vv = m - r * VV;
                int rg = row_base + r; if (rg >= BB) rg = BB - 1;
                const float4* p = reinterpret_cast<const float4*>(
                    src_ptr(vv, rg, s_fts, t_fts, s_h_fts, t_h_fts, s_neg_fts, t_neg_fts));
                stg[i] = p[(k0 >> 2) + q];
            }
        }
        const float* xb = sm.u.xT[kc & 1];
#pragma unroll
        for (int l = 0; l < FC; ++l) {
            const int k = kc * FC + l;
            const float4* xr = reinterpret_cast<const float4*>(xb + l * MVP) + mgrp * 2;
            float4 xa = xr[0];
            float4 xc = xr[1];
            const float4* wr = reinterpret_cast<const float4*>(sm.W + k * EE + n0);
            float4 w0 = wr[0], w1 = wr[1];
            float2 wp0 = make_float2(w0.x, w0.y), wp1 = make_float2(w0.z, w0.w);
            float2 wp2 = make_float2(w1.x, w1.y), wp3 = make_float2(w1.z, w1.w);
#define STEPX(xs, ai) { float2 xx = make_float2(xs, xs);      \
            acc[ai][0] = ffma2(xx, wp0, acc[ai][0]);          \
            acc[ai][1] = ffma2(xx, wp1, acc[ai][1]);          \
            acc[ai][2] = ffma2(xx, wp2, acc[ai][2]);          \
            acc[ai][3] = ffma2(xx, wp3, acc[ai][3]); }
            STEPX(xa.x, 0) STEPX(xa.y, 1) STEPX(xa.z, 2) STEPX(xa.w, 3)
            STEPX(xc.x, 4) STEPX(xc.y, 5) STEPX(xc.z, 6) STEPX(xc.w, 7)
#undef STEPX
        }
        if (kc + 1 < NCHUNK) {
            float* b = sm.u.xT[(kc + 1) & 1];
#pragma unroll
            for (int i = 0; i < 8; ++i) {
                int id = tid + i * NT;
                int m = id >> 2, q = id & 3;
                b[(4 * q + 0) * MVP + m] = stg[i].x;
                b[(4 * q + 1) * MVP + m] = stg[i].y;
                b[(4 * q + 2) * MVP + m] = stg[i].z;
                b[(4 * q + 3) * MVP + m] = stg[i].w;
            }
        }
        __syncthreads();
    }

    // ---- Phase 2a: emb stores, sqnorms, a-projections (quad shuffles) ----
#pragma unroll
    for (int mi = 0; mi < 8; ++mi) {
        const int m = m0 + mi;
        float2* e2 = reinterpret_cast<float2*>(sm.u.emb + m * ESTR + n0);
        e2[0] = acc[mi][0]; e2[1] = acc[mi][1];
        e2[2] = acc[mi][2]; e2[3] = acc[mi][3];

        float s = acc[mi][0].x * acc[mi][0].x + acc[mi][0].y * acc[mi][0].y
                + acc[mi][1].x * acc[mi][1].x + acc[mi][1].y * acc[mi][1].y
                + acc[mi][2].x * acc[mi][2].x + acc[mi][2].y * acc[mi][2].y
                + acc[mi][3].x * acc[mi][3].x + acc[mi][3].y * acc[mi][3].y;
        s += __shfl_xor_sync(0xFFFFFFFFu, s, 1);
        s += __shfl_xor_sync(0xFFFFFFFFu, s, 2);
        if (ngrp == 0) sm.sq[m] = s;

        const int r = m / VV;
        const int vv = m - r * VV;
        const float* av = sm.avec + ((vv < 2) ? 0 : EE) + n0;
        float d = acc[mi][0].x * av[0] + acc[mi][0].y * av[1]
                + acc[mi][1].x * av[2] + acc[mi][1].y * av[3]
                + acc[mi][2].x * av[4] + acc[mi][2].y * av[5]
                + acc[mi][3].x * av[6] + acc[mi][3].y * av[7];
        d += __shfl_xor_sync(0xFFFFFFFFu, d, 1);
        d += __shfl_xor_sync(0xFFFFFFFFu, d, 2);
        if (ngrp == 0 && vv < 6) sm.dots[r * 6 + vv] = d;
    }
    __syncthreads();

    // ---- Phase 2b: per-row attention weights ----
    if (tid < ROWS) {
        const int r = tid;
        int rg = row_base + r; if (rg >= BB) rg = BB - 1;
        const float ds = sm.deltas[0];
        const float dt = sm.deltas[1];
        const float et = event_time[rg];

        float dts0 = fabsf(et - s_h_times[rg * 2 + 0]);
        float dts1 = fabsf(et - s_h_times[rg * 2 + 1]);
        float sc0 = sm.dots[r * 6 + 0] + sm.dots[r * 6 + 2];
        float sc1 = sm.dots[r * 6 + 0] + sm.dots[r * 6 + 3];
        float sim0 = expf(-ds * dts0) * sc0; sim0 = (sim0 > 0.f) ? sim0 : 0.2f * sim0;
        float sim1 = expf(-ds * dts1) * sc1; sim1 = (sim1 > 0.f) ? sim1 : 0.2f * sim1;
        float mx = fmaxf(sim0, sim1);
        float e0 = expf(sim0 - mx), e1 = expf(sim1 - mx);
        float inv = 1.f / (e0 + e1);
        sm.wts[r * 4 + 0] = e0 * inv * expf(ds * dts0) * s_h_mask[rg * 2 + 0];
        sm.wts[r * 4 + 1] = e1 * inv * expf(ds * dts1) * s_h_mask[rg * 2 + 1];

        float dtt0 = fabsf(et - t_h_times[rg * 2 + 0]);
        float dtt1 = fabsf(et - t_h_times[rg * 2 + 1]);
        float tc0 = sm.dots[r * 6 + 1] + sm.dots[r * 6 + 4];
        float tc1 = sm.dots[r * 6 + 1] + sm.dots[r * 6 + 5];
        float tm0 = expf(-dt * dtt0) * tc0; tm0 = (tm0 > 0.f) ? tm0 : 0.2f * tm0;
        float tm1 = expf(-dt * dtt1) * tc1; tm1 = (tm1 > 0.f) ? tm1 : 0.2f * tm1;
        float mx2 = fmaxf(tm0, tm1);
        float f0 = expf(tm0 - mx2), f1 = expf(tm1 - mx2);
        float inv2 = 1.f / (f0 + f1);
        sm.wts[r * 4 + 2] = f0 * inv2 * expf(dt * dtt0) * t_h_mask[rg * 2 + 0];
        sm.wts[r * 4 + 3] = f1 * inv2 * expf(dt * dtt1) * t_h_mask[rg * 2 + 1];
    }
    __syncthreads();

    // ---- Phase 2c: 21 outputs per row ----
    for (int it = tid; it < ROWS * 21; it += NT) {
        const int r = it / 21;
        const int k = it % 21;
        const int rg = row_base + r;
        if (rg >= BB) continue;
        const float* base = sm.u.emb + r * VV * ESTR;

        if (k == 0) {
            const float* es  = base;
            const float* etb = base + 1 * ESTR;
            const float* h0  = base + 2 * ESTR;
            const float* h1  = base + 3 * ESTR;
            float pm = 0.f, pa0 = 0.f, pa1 = 0.f;
#pragma unroll
            for (int e = 0; e < EE; ++e) {
                float te = etb[e];
                float d0 = es[e] - te; pm  -= d0 * d0;
                float d1 = h0[e] - te; pa0 -= d1 * d1;
                float d2 = h1[e] - te; pa1 -= d2 * d2;
            }
            out[rg] = pm + sm.wts[r * 4 + 0] * pa0 + sm.wts[r * 4 + 1] * pa1;
        } else if (k <= 10) {
            const int n = k - 1;
            const float* en = base + (16 + n) * ESTR;
            const float* es = base;
            const float* h0 = base + 2 * ESTR;
            const float* h1 = base + 3 * ESTR;
            float d_s = 0.f, d0 = 0.f, d1 = 0.f;
#pragma unroll
            for (int e = 0; e < EE; ++e) {
                float x = en[e];
                d_s += es[e] * x;
                d0  += h0[e] * x;
                d1  += h1[e] * x;
            }
            float sqn = sm.sq[r * VV + 16 + n];
            float nmu = -(sm.sq[r * VV + 0] + sqn - 2.f * d_s);
            float na0 = -(sm.sq[r * VV + 2] + sqn - 2.f * d0);
            float na1 = -(sm.sq[r * VV + 3] + sqn - 2.f * d1);
            out[BB + (long)rg * NNEG + n] =
                nmu + sm.wts[r * 4 + 0] * na0 + sm.wts[r * 4 + 1] * na1;
        } else {
            const int n = k - 11;
            const float* en  = base + (6 + n) * ESTR;
            const float* et2 = base + 1 * ESTR;
            const float* h0  = base + 4 * ESTR;
            const float* h1  = base + 5 * ESTR;
            float d_t = 0.f, d0 = 0.f, d1 = 0.f;
#pragma unroll
            for (int e = 0; e < EE; ++e) {
                float x = en[e];
                d_t += et2[e] * x;
                d0  += h0[e] * x;
                d1  += h1[e] * x;
            }
            float sqn = sm.sq[r * VV + 6 + n];
            float nmu = -(sm.sq[r * VV + 1] + sqn - 2.f * d_t);
            float na0 = -(sm.sq[r * VV + 4] + sqn - 2.f * d0);
            float na1 = -(sm.sq[r * VV + 5] + sqn - 2.f * d1);
            out[BB + (long)BB * NNEG + (long)rg * NNEG + n] =
                nmu + sm.wts[r * 4 + 2] * na0 + sm.wts[r * 4 + 3] * na1;
        }
    }
}

extern "C" void kernel_launch(void* const* d_in, const int* in_sizes, int n_in,
                              void* d_out, int out_size)
{
    const float* s_fts      = (const float*)d_in[0];
    const float* t_fts      = (const float*)d_in[1];
    const float* s_h_fts    = (const float*)d_in[2];
    const float* t_h_fts    = (const float*)d_in[3];
    const float* s_neg_fts  = (const float*)d_in[4];
    const float* t_neg_fts  = (const float*)d_in[5];
    const float* event_time = (const float*)d_in[6];
    const float* s_h_times  = (const float*)d_in[7];
    const float* t_h_times  = (const float*)d_in[8];
    const float* s_h_mask   = (const float*)d_in[9];
    const float* t_h_mask   = (const float*)d_in[10];
    const float* W_fts      = (const float*)d_in[11];
    const float* b_fts      = (const float*)d_in[12];
    const float* a_vec      = (const float*)d_in[13];
    const float* delta_s    = (const float*)d_in[14];
    const float* delta_t    = (const float*)d_in[15];
    float* out = (float*)d_out;

    const int smem_bytes = (int)sizeof(SmemT);
    cudaFuncSetAttribute(mmdne_kernel,
                         cudaFuncAttributeMaxDynamicSharedMemorySize, smem_bytes);

    const int nblocks = (BB + ROWS - 1) / ROWS;  // 1563
    mmdne_kernel<<<nblocks, NT, smem_bytes>>>(
        s_fts, t_fts, s_h_fts, t_h_fts, s_neg_fts, t_neg_fts,
        event_time, s_h_times, t_h_times, s_h_mask, t_h_mask,
        W_fts, b_fts, a_vec, delta_s, delta_t, out);
}

// round 4
// speedup vs baseline: 1.7644x; 1.4122x over previous
#include <cuda_runtime.h>
#include <cstdint>

// MMDNE fused kernel, R4.
// R3 -> R4: hoisted staging addresses (no per-chunk int div), FC=16->8
// (smaller stg register footprint, conflict-free STS transpose), skewed
// x layout f(m)=m+(m>>5)*4 (conflict-free mainloop LDS.128), manual
// inner-loop prefetch.

#define BB   50000
#define FF   128
#define EE   32
#define HH   2
#define NNEG 10
#define VV   26              // vector-rows per batch row
#define ROWS 32              // batch rows per block
#define MV   (ROWS * VV)     // 832
#define NT   416             // threads (13 warps)
#define ESTR 34              // emb stride
#define MVP2 940             // skewed xT row stride (words, mult of 4)
#define FC   8               // k-chunk
#define NCHUNK (FF / FC)     // 16

struct SmemT {
    float W[FF * EE];        // [k][e], 16KB
    float bias[EE];
    float avec[2 * EE];
    float deltas[2];
    float sq[MV];
    float dots[ROWS * 6];
    float wts[ROWS * 4];
    alignas(16) union {
        float xT[2][FC * MVP2];  // 2*7520 floats (staging, mainloop only)
        float emb[MV * ESTR];    // 28288 floats (epilogue only)
    } u;
};

__device__ __forceinline__ float2 ffma2(float2 x, float2 w, float2 c) {
#if __CUDA_ARCH__ >= 1000
    unsigned long long xu = *reinterpret_cast<unsigned long long*>(&x);
    unsigned long long wu = *reinterpret_cast<unsigned long long*>(&w);
    unsigned long long cu = *reinterpret_cast<unsigned long long*>(&c);
    unsigned long long du;
    asm("fma.rn.f32x2 %0, %1, %2, %3;" : "=l"(du) : "l"(xu), "l"(wu), "l"(cu));
    return *reinterpret_cast<float2*>(&du);
#else
    return make_float2(fmaf(x.x, w.x, c.x), fmaf(x.y, w.y, c.y));
#endif
}

__device__ __forceinline__ const float* src_ptr(
    int v, int rg,
    const float* s_fts, const float* t_fts,
    const float* s_h, const float* t_h,
    const float* s_n, const float* t_n)
{
    if (v == 0)  return s_fts + (long)rg * FF;
    if (v == 1)  return t_fts + (long)rg * FF;
    if (v < 4)   return s_h + ((long)rg * HH + (v - 2)) * FF;
    if (v < 6)   return t_h + ((long)rg * HH + (v - 4)) * FF;
    if (v < 16)  return s_n + ((long)rg * NNEG + (v - 6)) * FF;
    return t_n + ((long)rg * NNEG + (v - 16)) * FF;
}

__global__ void __launch_bounds__(NT, 1) mmdne_kernel(
    const float* __restrict__ s_fts, const float* __restrict__ t_fts,
    const float* __restrict__ s_h_fts, const float* __restrict__ t_h_fts,
    const float* __restrict__ s_neg_fts, const float* __restrict__ t_neg_fts,
    const float* __restrict__ event_time,
    const float* __restrict__ s_h_times, const float* __restrict__ t_h_times,
    const float* __restrict__ s_h_mask, const float* __restrict__ t_h_mask,
    const float* __restrict__ W_fts, const float* __restrict__ b_fts,
    const float* __restrict__ a_vec,
    const float* __restrict__ delta_s, const float* __restrict__ delta_t,
    float* __restrict__ out)
{
    extern __shared__ char smem_raw[];
    SmemT& sm = *reinterpret_cast<SmemT*>(smem_raw);
    const int tid = threadIdx.x;
    const int row_base = blockIdx.x * ROWS;

    // ---- Phase 0: stage W, bias, a, deltas ----
    {
        const float4* Wg = reinterpret_cast<const float4*>(W_fts);
        float4* Ws = reinterpret_cast<float4*>(sm.W);
        for (int i = tid; i < FF * EE / 4; i += NT) Ws[i] = Wg[i];
    }
    if (tid < EE)      sm.bias[tid] = b_fts[tid];
    if (tid < 2 * EE)  sm.avec[tid] = a_vec[tid];
    if (tid == 0) { sm.deltas[0] = delta_s[0]; sm.deltas[1] = delta_t[0]; }

    const int ngrp = tid & 3;          // n0 = 8*ngrp
    const int mgrp = tid >> 2;         // m0 = 8*mgrp
    const int m0 = mgrp * 8;
    const int n0 = ngrp * 8;
    const int fm0 = m0 + ((mgrp >> 2) << 2);   // skewed col of m0 (8mgrp+(mgrp>>2)*4)

    // ---- hoisted staging descriptors (loop-invariant) ----
    // Per chunk each thread moves 4 float4: element id = tid + i*NT (0..1663),
    // q = id&1 selects which float4 of the 2-per-row chunk, m = id>>1 (row).
    const float4* sptr[4];
    int sbase[4];
#pragma unroll
    for (int i = 0; i < 4; ++i) {
        int id = tid + i * NT;
        int q = id & 1, m = id >> 1;
        int r = m / VV, vv = m - r * VV;
        int rg = row_base + r; if (rg >= BB) rg = BB - 1;
        sptr[i] = reinterpret_cast<const float4*>(
            src_ptr(vv, rg, s_fts, t_fts, s_h_fts, t_h_fts, s_neg_fts, t_neg_fts)) + q;
        int fm = m + ((m >> 5) << 2);
        sbase[i] = (4 * q) * MVP2 + fm;        // rows 4q+j, j=0..3
    }

    // ---- stage chunk 0 ----
    {
        float4 stg[4];
#pragma unroll
        for (int i = 0; i < 4; ++i) stg[i] = sptr[i][0];
        float* b = sm.u.xT[0];
#pragma unroll
        for (int i = 0; i < 4; ++i) {
            b[sbase[i] + 0 * MVP2] = stg[i].x;
            b[sbase[i] + 1 * MVP2] = stg[i].y;
            b[sbase[i] + 2 * MVP2] = stg[i].z;
            b[sbase[i] + 3 * MVP2] = stg[i].w;
        }
    }
    __syncthreads();

    // ---- acc init from bias ----
    float2 acc[8][4];
    {
        float2 b0 = make_float2(sm.bias[n0 + 0], sm.bias[n0 + 1]);
        float2 b1 = make_float2(sm.bias[n0 + 2], sm.bias[n0 + 3]);
        float2 b2 = make_float2(sm.bias[n0 + 4], sm.bias[n0 + 5]);
        float2 b3 = make_float2(sm.bias[n0 + 6], sm.bias[n0 + 7]);
#pragma unroll
        for (int mi = 0; mi < 8; ++mi) {
            acc[mi][0] = b0; acc[mi][1] = b1; acc[mi][2] = b2; acc[mi][3] = b3;
        }
    }

    // ---- mainloop over 16 k-chunks ----
    float4 stg[4];
#pragma unroll 1
    for (int kc = 0; kc < NCHUNK; ++kc) {
        if (kc + 1 < NCHUNK) {
            const int idx = 2 * (kc + 1);
#pragma unroll
            for (int i = 0; i < 4; ++i) stg[i] = sptr[i][idx];
        }
        const float* xb = sm.u.xT[kc & 1];
        const float* wb = sm.W + (kc * FC) * EE + n0;

        // prefetch l=0
        float4 xa = *reinterpret_cast<const float4*>(xb + fm0);
        float4 xc = *reinterpret_cast<const float4*>(xb + fm0 + 4);
        float4 w0 = *reinterpret_cast<const float4*>(wb);
        float4 w1 = *reinterpret_cast<const float4*>(wb + 4);
#pragma unroll
        for (int l = 0; l < FC; ++l) {
            float4 nxa, nxc, nw0, nw1;
            if (l + 1 < FC) {
                const float* xr = xb + (l + 1) * MVP2 + fm0;
                nxa = *reinterpret_cast<const float4*>(xr);
                nxc = *reinterpret_cast<const float4*>(xr + 4);
                const float* wr = wb + (l + 1) * EE;
                nw0 = *reinterpret_cast<const float4*>(wr);
                nw1 = *reinterpret_cast<const float4*>(wr + 4);
            }
            float2 wp0 = make_float2(w0.x, w0.y), wp1 = make_float2(w0.z, w0.w);
            float2 wp2 = make_float2(w1.x, w1.y), wp3 = make_float2(w1.z, w1.w);
#define STEPX(xs, ai) { float2 xx = make_float2(xs, xs);      \
            acc[ai][0] = ffma2(xx, wp0, acc[ai][0]);          \
            acc[ai][1] = ffma2(xx, wp1, acc[ai][1]);          \
            acc[ai][2] = ffma2(xx, wp2, acc[ai][2]);          \
            acc[ai][3] = ffma2(xx, wp3, acc[ai][3]); }
            STEPX(xa.x, 0) STEPX(xa.y, 1) STEPX(xa.z, 2) STEPX(xa.w, 3)
            STEPX(xc.x, 4) STEPX(xc.y, 5) STEPX(xc.z, 6) STEPX(xc.w, 7)
#undef STEPX
            if (l + 1 < FC) { xa = nxa; xc = nxc; w0 = nw0; w1 = nw1; }
        }
        if (kc + 1 < NCHUNK) {
            float* b = sm.u.xT[(kc + 1) & 1];
#pragma unroll
            for (int i = 0; i < 4; ++i) {
                b[sbase[i] + 0 * MVP2] = stg[i].x;
                b[sbase[i] + 1 * MVP2] = stg[i].y;
                b[sbase[i] + 2 * MVP2] = stg[i].z;
                b[sbase[i] + 3 * MVP2] = stg[i].w;
            }
        }
        __syncthreads();
    }

    // ---- Phase 2a: emb stores, sqnorms, a-projections (quad shuffles) ----
    {
        int rr = m0 / VV;
        int vvv = m0 - rr * VV;
#pragma unroll
        for (int mi = 0; mi < 8; ++mi) {
            const int m = m0 + mi;
            float2* e2 = reinterpret_cast<float2*>(sm.u.emb + m * ESTR + n0);
            e2[0] = acc[mi][0]; e2[1] = acc[mi][1];
            e2[2] = acc[mi][2]; e2[3] = acc[mi][3];

            float s = acc[mi][0].x * acc[mi][0].x + acc[mi][0].y * acc[mi][0].y
                    + acc[mi][1].x * acc[mi][1].x + acc[mi][1].y * acc[mi][1].y
                    + acc[mi][2].x * acc[mi][2].x + acc[mi][2].y * acc[mi][2].y
                    + acc[mi][3].x * acc[mi][3].x + acc[mi][3].y * acc[mi][3].y;
            s += __shfl_xor_sync(0xFFFFFFFFu, s, 1);
            s += __shfl_xor_sync(0xFFFFFFFFu, s, 2);
            if (ngrp == 0) sm.sq[m] = s;

            const float* av = sm.avec + ((vvv < 2) ? 0 : EE) + n0;
            float d = acc[mi][0].x * av[0] + acc[mi][0].y * av[1]
                    + acc[mi][1].x * av[2] + acc[mi][1].y * av[3]
                    + acc[mi][2].x * av[4] + acc[mi][2].y * av[5]
                    + acc[mi][3].x * av[6] + acc[mi][3].y * av[7];
            d += __shfl_xor_sync(0xFFFFFFFFu, d, 1);
            d += __shfl_xor_sync(0xFFFFFFFFu, d, 2);
            if (ngrp == 0 && vvv < 6) sm.dots[rr * 6 + vvv] = d;

            if (++vvv == VV) { vvv = 0; ++rr; }
        }
    }
    __syncthreads();

    // ---- Phase 2b: per-row attention weights ----
    if (tid < ROWS) {
        const int r = tid;
        int rg = row_base + r; if (rg >= BB) rg = BB - 1;
        const float ds = sm.deltas[0];
        const float dt = sm.deltas[1];
        const float et = event_time[rg];

        float dts0 = fabsf(et - s_h_times[rg * 2 + 0]);
        float dts1 = fabsf(et - s_h_times[rg * 2 + 1]);
        float sc0 = sm.dots[r * 6 + 0] + sm.dots[r * 6 + 2];
        float sc1 = sm.dots[r * 6 + 0] + sm.dots[r * 6 + 3];
        float sim0 = expf(-ds * dts0) * sc0; sim0 = (sim0 > 0.f) ? sim0 : 0.2f * sim0;
        float sim1 = expf(-ds * dts1) * sc1; sim1 = (sim1 > 0.f) ? sim1 : 0.2f * sim1;
        float mx = fmaxf(sim0, sim1);
        float e0 = expf(sim0 - mx), e1 = expf(sim1 - mx);
        float inv = 1.f / (e0 + e1);
        sm.wts[r * 4 + 0] = e0 * inv * expf(ds * dts0) * s_h_mask[rg * 2 + 0];
        sm.wts[r * 4 + 1] = e1 * inv * expf(ds * dts1) * s_h_mask[rg * 2 + 1];

        float dtt0 = fabsf(et - t_h_times[rg * 2 + 0]);
        float dtt1 = fabsf(et - t_h_times[rg * 2 + 1]);
        float tc0 = sm.dots[r * 6 + 1] + sm.dots[r * 6 + 4];
        float tc1 = sm.dots[r * 6 + 1] + sm.dots[r * 6 + 5];
        float tm0 = expf(-dt * dtt0) * tc0; tm0 = (tm0 > 0.f) ? tm0 : 0.2f * tm0;
        float tm1 = expf(-dt * dtt1) * tc1; tm1 = (tm1 > 0.f) ? tm1 : 0.2f * tm1;
        float mx2 = fmaxf(tm0, tm1);
        float f0 = expf(tm0 - mx2), f1 = expf(tm1 - mx2);
        float inv2 = 1.f / (f0 + f1);
        sm.wts[r * 4 + 2] = f0 * inv2 * expf(dt * dtt0) * t_h_mask[rg * 2 + 0];
        sm.wts[r * 4 + 3] = f1 * inv2 * expf(dt * dtt1) * t_h_mask[rg * 2 + 1];
    }
    __syncthreads();

    // ---- Phase 2c: 21 outputs per row ----
    for (int it = tid; it < ROWS * 21; it += NT) {
        const int r = it / 21;
        const int k = it % 21;
        const int rg = row_base + r;
        if (rg >= BB) continue;
        const float* base = sm.u.emb + r * VV * ESTR;

        if (k == 0) {
            const float* es  = base;
            const float* etb = base + 1 * ESTR;
            const float* h0  = base + 2 * ESTR;
            const float* h1  = base + 3 * ESTR;
            float pm = 0.f, pa0 = 0.f, pa1 = 0.f;
#pragma unroll
            for (int e = 0; e < EE; ++e) {
                float te = etb[e];
                float d0 = es[e] - te; pm  -= d0 * d0;
                float d1 = h0[e] - te; pa0 -= d1 * d1;
                float d2 = h1[e] - te; pa1 -= d2 * d2;
            }
            out[rg] = pm + sm.wts[r * 4 + 0] * pa0 + sm.wts[r * 4 + 1] * pa1;
        } else if (k <= 10) {
            const int n = k - 1;
            const float* en = base + (16 + n) * ESTR;
            const float* es = base;
            const float* h0 = base + 2 * ESTR;
            const float* h1 = base + 3 * ESTR;
            float d_s = 0.f, d0 = 0.f, d1 = 0.f;
#pragma unroll
            for (int e = 0; e < EE; ++e) {
                float x = en[e];
                d_s += es[e] * x;
                d0  += h0[e] * x;
                d1  += h1[e] * x;
            }
            float sqn = sm.sq[r * VV + 16 + n];
            float nmu = -(sm.sq[r * VV + 0] + sqn - 2.f * d_s);
            float na0 = -(sm.sq[r * VV + 2] + sqn - 2.f * d0);
            float na1 = -(sm.sq[r * VV + 3] + sqn - 2.f * d1);
            out[BB + (long)rg * NNEG + n] =
                nmu + sm.wts[r * 4 + 0] * na0 + sm.wts[r * 4 + 1] * na1;
        } else {
            const int n = k - 11;
            const float* en  = base + (6 + n) * ESTR;
            const float* et2 = base + 1 * ESTR;
            const float* h0  = base + 4 * ESTR;
            const float* h1  = base + 5 * ESTR;
            float d_t = 0.f, d0 = 0.f, d1 = 0.f;
#pragma unroll
            for (int e = 0; e < EE; ++e) {
                float x = en[e];
                d_t += et2[e] * x;
                d0  += h0[e] * x;
                d1  += h1[e] * x;
            }
            float sqn = sm.sq[r * VV + 6 + n];
            float nmu = -(sm.sq[r * VV + 1] + sqn - 2.f * d_t);
            float na0 = -(sm.sq[r * VV + 4] + sqn - 2.f * d0);
            float na1 = -(sm.sq[r * VV + 5] + sqn - 2.f * d1);
            out[BB + (long)BB * NNEG + (long)rg * NNEG + n] =
                nmu + sm.wts[r * 4 + 2] * na0 + sm.wts[r * 4 + 3] * na1;
        }
    }
}

extern "C" void kernel_launch(void* const* d_in, const int* in_sizes, int n_in,
                              void* d_out, int out_size)
{
    const float* s_fts      = (const float*)d_in[0];
    const float* t_fts      = (const float*)d_in[1];
    const float* s_h_fts    = (const float*)d_in[2];
    const float* t_h_fts    = (const float*)d_in[3];
    const float* s_neg_fts  = (const float*)d_in[4];
    const float* t_neg_fts  = (const float*)d_in[5];
    const float* event_time = (const float*)d_in[6];
    const float* s_h_times  = (const float*)d_in[7];
    const float* t_h_times  = (const float*)d_in[8];
    const float* s_h_mask   = (const float*)d_in[9];
    const float* t_h_mask   = (const float*)d_in[10];
    const float* W_fts      = (const float*)d_in[11];
    const float* b_fts      = (const float*)d_in[12];
    const float* a_vec      = (const float*)d_in[13];
    const float* delta_s    = (const float*)d_in[14];
    const float* delta_t    = (const float*)d_in[15];
    float* out = (float*)d_out;

    const int smem_bytes = (int)sizeof(SmemT);
    cudaFuncSetAttribute(mmdne_kernel,
                         cudaFuncAttributeMaxDynamicSharedMemorySize, smem_bytes);

    const int nblocks = (BB + ROWS - 1) / ROWS;  // 1563
    mmdne_kernel<<<nblocks, NT, smem_bytes>>>(
        s_fts, t_fts, s_h_fts, t_h_fts, s_neg_fts, t_neg_fts,
        event_time, s_h_times, t_h_times, s_h_mask, t_h_mask,
        W_fts, b_fts, a_vec, delta_s, delta_t, out);
}

// round 7
// speedup vs baseline: 1.8396x; 1.0426x over previous
#include <cuda_runtime.h>
#include <cstdint>

// MMDNE fused kernel, R7 (= R6 resubmit after environmental bench failure;
// dead statement removed). mma.sync tf32 2-term-split GEMM (HMMA path;
// tcgen05 unavailable: harness targets compute_103 without 'a').
// Block = 416 thr (13 warps), 32 batch rows -> 832 vector-rows grouped by
// tensor span: [s 0..31][t 32..63][s_h 64..127][t_h 128..191]
// [s_n 192..511][t_n 512..831]. Warp w computes rows 64w..64w+63 (4 m16
// tiles) x 32 cols, K=128 in 4 chunks of 32 staged to smem (coalesced,
// div-free). Per k-step: 3 MMAs (xh*Wh, xh*Wl, xl*Wh), fp32 accum.

#define BB   50000
#define FF   128
#define EE   32
#define NNEG 10
#define ROWS 32
#define MV   832
#define NT   416
#define XSTR 36              // xs row stride (words): bank-safe + 16B mult
#define ESTR 34              // emb row stride (even -> 8B float2 stores)
#define TFMASK 0xFFFFE000u

struct SmemT {
    float whi[4096];         // W hi fragments, lane-major per (kstep,ntile)
    float wlo[4096];         // W lo fragments
    float bias[EE];
    float avec[2 * EE];
    float deltas[2];
    float sq[MV];
    float dots[ROWS * 6];
    float wts[ROWS * 4];
    alignas(16) union {
        float xs[MV * XSTR];     // 29952 floats: staging (k-chunk of 32)
        float emb[MV * ESTR];    // 28288 floats: epilogue
    } u;
};

#define MMA_TF32(d, a0, a1, a2, a3, b0, b1)                               \
    asm volatile("mma.sync.aligned.m16n8k8.row.col.f32.tf32.tf32.f32 "    \
        "{%0,%1,%2,%3}, {%4,%5,%6,%7}, {%8,%9}, {%0,%1,%2,%3};"           \
        : "+f"(d[0]), "+f"(d[1]), "+f"(d[2]), "+f"(d[3])                  \
        : "r"(a0), "r"(a1), "r"(a2), "r"(a3), "r"(b0), "r"(b1))

__device__ __forceinline__ int imin(int a, int b) { return a < b ? a : b; }

__global__ void __launch_bounds__(NT, 1) mmdne_kernel(
    const float* __restrict__ s_fts, const float* __restrict__ t_fts,
    const float* __restrict__ s_h_fts, const float* __restrict__ t_h_fts,
    const float* __restrict__ s_neg_fts, const float* __restrict__ t_neg_fts,
    const float* __restrict__ event_time,
    const float* __restrict__ s_h_times, const float* __restrict__ t_h_times,
    const float* __restrict__ s_h_mask, const float* __restrict__ t_h_mask,
    const float* __restrict__ W_fts, const float* __restrict__ b_fts,
    const float* __restrict__ a_vec,
    const float* __restrict__ delta_s, const float* __restrict__ delta_t,
    float* __restrict__ out)
{
    extern __shared__ char smem_raw[];
    SmemT& sm = *reinterpret_cast<SmemT*>(smem_raw);
    const int tid  = threadIdx.x;
    const int wid  = tid >> 5;
    const int lane = tid & 31;
    const int g    = lane >> 2;       // groupID (row within fragment)
    const int tg   = lane & 3;        // thread-in-group (col within fragment)
    const int row_base = blockIdx.x * ROWS;

    // ---- Phase 0: params + W -> hi/lo fragments (lane-major layout) ----
    if (tid < EE)     sm.bias[tid] = b_fts[tid];
    if (tid < 2 * EE) sm.avec[tid] = a_vec[tid];
    if (tid == 0) { sm.deltas[0] = delta_s[0]; sm.deltas[1] = delta_t[0]; }
    for (int idx = tid; idx < 4096; idx += NT) {
        int s   = idx >> 8;             // kstep 0..15
        int rem = idx & 255;
        int ntl = rem >> 6;             // ntile 0..3
        int l   = (rem >> 1) & 31;      // lane
        int wh  = idx & 1;              // 0 -> b0 (k=8s+tg'), 1 -> b1 (+4)
        int gg  = l >> 2, tt = l & 3;
        int k   = 8 * s + tt + (wh ? 4 : 0);
        int e   = 8 * ntl + gg;
        float w = W_fts[k * EE + e];
        uint32_t hb = __float_as_uint(w) & TFMASK;
        sm.whi[idx] = __uint_as_float(hb);
        sm.wlo[idx] = w - __uint_as_float(hb);
    }

    float acc[4][4][4];
#pragma unroll
    for (int mt = 0; mt < 4; ++mt)
#pragma unroll
        for (int nt = 0; nt < 4; ++nt)
#pragma unroll
            for (int j = 0; j < 4; ++j) acc[mt][nt][j] = 0.f;

    // ---- K-chunk loop: stage 32 k-cols of all 832 rows, then MMA ----
    for (int c = 0; c < 4; ++c) {
        __syncthreads();   // xs free (prev chunk consumed / whi written)
#pragma unroll
        for (int i = 0; i < 16; ++i) {
            int idx = tid + i * NT;            // 0..6655
            int m = idx >> 3;                  // vector-row 0..831
            int q = idx & 7;                   // float4 index within 32-k chunk
            const float* gp;
            if (m < 32)       gp = s_fts     + (long)imin(row_base + m,            BB - 1)      * FF;
            else if (m < 64)  gp = t_fts     + (long)imin(row_base + m - 32,       BB - 1)      * FF;
            else if (m < 128) gp = s_h_fts   + (long)imin(row_base * 2 + m - 64,   2 * BB - 1)  * FF;
            else if (m < 192) gp = t_h_fts   + (long)imin(row_base * 2 + m - 128,  2 * BB - 1)  * FF;
            else if (m < 512) gp = s_neg_fts + (long)imin(row_base * 10 + m - 192, 10 * BB - 1) * FF;
            else              gp = t_neg_fts + (long)imin(row_base * 10 + m - 512, 10 * BB - 1) * FF;
            float4 v = *(reinterpret_cast<const float4*>(gp + 32 * c) + q);
            *reinterpret_cast<float4*>(&sm.u.xs[m * XSTR + 4 * q]) = v;
        }
        __syncthreads();

        const float* xw = sm.u.xs + (wid * 64) * XSTR;
#pragma unroll
        for (int kt = 0; kt < 4; ++kt) {
            const int sg = c * 4 + kt;
            uint32_t bh[4][2], bl[4][2];
#pragma unroll
            for (int nt = 0; nt < 4; ++nt) {
                const float* ph = &sm.whi[(sg * 4 + nt) * 64 + lane * 2];
                const float* pl = &sm.wlo[(sg * 4 + nt) * 64 + lane * 2];
                float2 h = *reinterpret_cast<const float2*>(ph);
                float2 lo = *reinterpret_cast<const float2*>(pl);
                bh[nt][0] = __float_as_uint(h.x);  bh[nt][1] = __float_as_uint(h.y);
                bl[nt][0] = __float_as_uint(lo.x); bl[nt][1] = __float_as_uint(lo.y);
            }
#pragma unroll
            for (int mt = 0; mt < 4; ++mt) {
                const float* ap = xw + (16 * mt + g) * XSTR + 8 * kt + tg;
                float a0f = ap[0];
                float a1f = ap[8 * XSTR];
                float a2f = ap[4];
                float a3f = ap[8 * XSTR + 4];
                uint32_t ah0 = __float_as_uint(a0f) & TFMASK;
                uint32_t ah1 = __float_as_uint(a1f) & TFMASK;
                uint32_t ah2 = __float_as_uint(a2f) & TFMASK;
                uint32_t ah3 = __float_as_uint(a3f) & TFMASK;
                uint32_t al0 = __float_as_uint(a0f - __uint_as_float(ah0));
                uint32_t al1 = __float_as_uint(a1f - __uint_as_float(ah1));
                uint32_t al2 = __float_as_uint(a2f - __uint_as_float(ah2));
                uint32_t al3 = __float_as_uint(a3f - __uint_as_float(ah3));
#pragma unroll
                for (int nt = 0; nt < 4; ++nt) {
                    MMA_TF32(acc[mt][nt], ah0, ah1, ah2, ah3, bh[nt][0], bh[nt][1]);
                    MMA_TF32(acc[mt][nt], ah0, ah1, ah2, ah3, bl[nt][0], bl[nt][1]);
                    MMA_TF32(acc[mt][nt], al0, al1, al2, al3, bh[nt][0], bh[nt][1]);
                }
            }
        }
    }
    __syncthreads();   // all warps done reading xs -> emb alias safe

    // ---- Epilogue A: bias add, emb stores, sqnorms, a-projections ----
#pragma unroll
    for (int mt = 0; mt < 4; ++mt) {
        const int r1 = wid * 64 + mt * 16 + g;
        const int r2 = r1 + 8;
        const float* av1 = sm.avec + ((r1 < 64) ? 0 : EE);
        const float* av2 = sm.avec + ((r2 < 64) ? 0 : EE);
        float s1 = 0.f, s2 = 0.f, d1 = 0.f, d2 = 0.f;
#pragma unroll
        for (int nt = 0; nt < 4; ++nt) {
            const int col = nt * 8 + tg * 2;
            float b0 = sm.bias[col], b1v = sm.bias[col + 1];
            float e0 = acc[mt][nt][0] + b0, e1 = acc[mt][nt][1] + b1v;
            float e2 = acc[mt][nt][2] + b0, e3 = acc[mt][nt][3] + b1v;
            *reinterpret_cast<float2*>(&sm.u.emb[r1 * ESTR + col]) = make_float2(e0, e1);
            *reinterpret_cast<float2*>(&sm.u.emb[r2 * ESTR + col]) = make_float2(e2, e3);
            s1 += e0 * e0 + e1 * e1;
            s2 += e2 * e2 + e3 * e3;
            d1 += e0 * av1[col] + e1 * av1[col + 1];
            d2 += e2 * av2[col] + e3 * av2[col + 1];
        }
        s1 += __shfl_xor_sync(0xFFFFFFFFu, s1, 1); s1 += __shfl_xor_sync(0xFFFFFFFFu, s1, 2);
        s2 += __shfl_xor_sync(0xFFFFFFFFu, s2, 1); s2 += __shfl_xor_sync(0xFFFFFFFFu, s2, 2);
        d1 += __shfl_xor_sync(0xFFFFFFFFu, d1, 1); d1 += __shfl_xor_sync(0xFFFFFFFFu, d1, 2);
        d2 += __shfl_xor_sync(0xFFFFFFFFu, d2, 1); d2 += __shfl_xor_sync(0xFFFFFFFFu, d2, 2);
        if (tg == 0) {
            sm.sq[r1] = s1;
            sm.sq[r2] = s2;
            // dots slot map: s->0, t->1, s_h->2+h, t_h->4+h
            int mm = r1; float dd = d1;
#pragma unroll
            for (int rep = 0; rep < 2; ++rep) {
                if (mm < 32)       sm.dots[mm * 6 + 0] = dd;
                else if (mm < 64)  sm.dots[(mm - 32) * 6 + 1] = dd;
                else if (mm < 128) sm.dots[((mm - 64) >> 1) * 6 + 2 + ((mm - 64) & 1)] = dd;
                else if (mm < 192) sm.dots[((mm - 128) >> 1) * 6 + 4 + ((mm - 128) & 1)] = dd;
                mm = r2; dd = d2;
            }
        }
    }
    __syncthreads();

    // ---- Epilogue B: per-row attention weights (32 threads) ----
    if (tid < ROWS) {
        const int r = tid;
        int rg = row_base + r; if (rg >= BB) rg = BB - 1;
        const float ds = sm.deltas[0];
        const float dt = sm.deltas[1];
        const float et = event_time[rg];

        float dts0 = fabsf(et - s_h_times[rg * 2 + 0]);
        float dts1 = fabsf(et - s_h_times[rg * 2 + 1]);
        float sc0 = sm.dots[r * 6 + 0] + sm.dots[r * 6 + 2];
        float sc1 = sm.dots[r * 6 + 0] + sm.dots[r * 6 + 3];
        float sim0 = expf(-ds * dts0) * sc0; sim0 = (sim0 > 0.f) ? sim0 : 0.2f * sim0;
        float sim1 = expf(-ds * dts1) * sc1; sim1 = (sim1 > 0.f) ? sim1 : 0.2f * sim1;
        float mx = fmaxf(sim0, sim1);
        float e0 = expf(sim0 - mx), e1 = expf(sim1 - mx);
        float inv = 1.f / (e0 + e1);
        sm.wts[r * 4 + 0] = e0 * inv * expf(ds * dts0) * s_h_mask[rg * 2 + 0];
        sm.wts[r * 4 + 1] = e1 * inv * expf(ds * dts1) * s_h_mask[rg * 2 + 1];

        float dtt0 = fabsf(et - t_h_times[rg * 2 + 0]);
        float dtt1 = fabsf(et - t_h_times[rg * 2 + 1]);
        float tc0 = sm.dots[r * 6 + 1] + sm.dots[r * 6 + 4];
        float tc1 = sm.dots[r * 6 + 1] + sm.dots[r * 6 + 5];
        float tm0 = expf(-dt * dtt0) * tc0; tm0 = (tm0 > 0.f) ? tm0 : 0.2f * tm0;
        float tm1 = expf(-dt * dtt1) * tc1; tm1 = (tm1 > 0.f) ? tm1 : 0.2f * tm1;
        float mx2 = fmaxf(tm0, tm1);
        float f0 = expf(tm0 - mx2), f1 = expf(tm1 - mx2);
        float inv2 = 1.f / (f0 + f1);
        sm.wts[r * 4 + 2] = f0 * inv2 * expf(dt * dtt0) * t_h_mask[rg * 2 + 0];
        sm.wts[r * 4 + 3] = f1 * inv2 * expf(dt * dtt1) * t_h_mask[rg * 2 + 1];
    }
    __syncthreads();

    // ---- Epilogue C: 21 outputs per row ----
    // Row map: s=r, t=32+r, s_h=64+2r+h, t_h=128+2r+h, s_n=192+10r+n, t_n=512+10r+n
    for (int it = tid; it < ROWS * 21; it += NT) {
        const int r = it / 21;
        const int k = it % 21;
        const int rg = row_base + r;
        if (rg >= BB) continue;
        const float* E = sm.u.emb;

        if (k == 0) {
            const float* es  = E + (r) * ESTR;
            const float* etb = E + (32 + r) * ESTR;
            const float* h0  = E + (64 + 2 * r) * ESTR;
            const float* h1  = E + (65 + 2 * r) * ESTR;
            float pm = 0.f, pa0 = 0.f, pa1 = 0.f;
#pragma unroll
            for (int e = 0; e < EE; ++e) {
                float te = etb[e];
                float d0 = es[e] - te; pm  -= d0 * d0;
                float d1 = h0[e] - te; pa0 -= d1 * d1;
                float d2 = h1[e] - te; pa1 -= d2 * d2;
            }
            out[rg] = pm + sm.wts[r * 4 + 0] * pa0 + sm.wts[r * 4 + 1] * pa1;
        } else if (k <= 10) {
            const int n = k - 1;
            const float* en = E + (512 + 10 * r + n) * ESTR;   // t_neg
            const float* es = E + (r) * ESTR;
            const float* h0 = E + (64 + 2 * r) * ESTR;
            const float* h1 = E + (65 + 2 * r) * ESTR;
            float d_s = 0.f, d0 = 0.f, d1 = 0.f;
#pragma unroll
            for (int e = 0; e < EE; ++e) {
                float x = en[e];
                d_s += es[e] * x;
                d0  += h0[e] * x;
                d1  += h1[e] * x;
            }
            float sqn = sm.sq[512 + 10 * r + n];
            float nmu = -(sm.sq[r] + sqn - 2.f * d_s);
            float na0 = -(sm.sq[64 + 2 * r] + sqn - 2.f * d0);
            float na1 = -(sm.sq[65 + 2 * r] + sqn - 2.f * d1);
            out[BB + (long)rg * NNEG + n] =
                nmu + sm.wts[r * 4 + 0] * na0 + sm.wts[r * 4 + 1] * na1;
        } else {
            const int n = k - 11;
            const float* en  = E + (192 + 10 * r + n) * ESTR;  // s_neg
            const float* et2 = E + (32 + r) * ESTR;
            const float* h0  = E + (128 + 2 * r) * ESTR;
            const float* h1  = E + (129 + 2 * r) * ESTR;
            float d_t = 0.f, d0 = 0.f, d1 = 0.f;
#pragma unroll
            for (int e = 0; e < EE; ++e) {
                float x = en[e];
                d_t += et2[e] * x;
                d0  += h0[e] * x;
                d1  += h1[e] * x;
            }
            float sqn = sm.sq[192 + 10 * r + n];
            float nmu = -(sm.sq[32 + r] + sqn - 2.f * d_t);
            float na0 = -(sm.sq[128 + 2 * r] + sqn - 2.f * d0);
            float na1 = -(sm.sq[129 + 2 * r] + sqn - 2.f * d1);
            out[BB + (long)BB * NNEG + (long)rg * NNEG + n] =
                nmu + sm.wts[r * 4 + 2] * na0 + sm.wts[r * 4 + 3] * na1;
        }
    }
}

extern "C" void kernel_launch(void* const* d_in, const int* in_sizes, int n_in,
                              void* d_out, int out_size)
{
    const float* s_fts      = (const float*)d_in[0];
    const float* t_fts      = (const float*)d_in[1];
    const float* s_h_fts    = (const float*)d_in[2];
    const float* t_h_fts    = (const float*)d_in[3];
    const float* s_neg_fts  = (const float*)d_in[4];
    const float* t_neg_fts  = (const float*)d_in[5];
    const float* event_time = (const float*)d_in[6];
    const float* s_h_times  = (const float*)d_in[7];
    const float* t_h_times  = (const float*)d_in[8];
    const float* s_h_mask   = (const float*)d_in[9];
    const float* t_h_mask   = (const float*)d_in[10];
    const float* W_fts      = (const float*)d_in[11];
    const float* b_fts      = (const float*)d_in[12];
    const float* a_vec      = (const float*)d_in[13];
    const float* delta_s    = (const float*)d_in[14];
    const float* delta_t    = (const float*)d_in[15];
    float* out = (float*)d_out;

    const int smem_bytes = (int)sizeof(SmemT);
    cudaFuncSetAttribute(mmdne_kernel,
                         cudaFuncAttributeMaxDynamicSharedMemorySize, smem_bytes);

    const int nblocks = (BB + ROWS - 1) / ROWS;  // 1563
    mmdne_kernel<<<nblocks, NT, smem_bytes>>>(
        s_fts, t_fts, s_h_fts, t_h_fts, s_neg_fts, t_neg_fts,
        event_time, s_h_times, t_h_times, s_h_mask, t_h_mask,
        W_fts, b_fts, a_vec, delta_s, delta_t, out);
}

// round 8
// speedup vs baseline: 2.6359x; 1.4329x over previous
#include <cuda_runtime.h>
#include <cstdint>

// MMDNE fused kernel, R8: tf32 2-term-split HMMA, halved block for 2 CTAs/SM.
// ROWS=16 -> MV=416 vector-rows, smem ~95.4KB/CTA, __launch_bounds__(416,2).
// Spans: [s 0..15][t 16..31][s_h 32..63][t_h 64..95][s_n 96..255][t_n 256..415].
// Warp w: rows 32w..32w+31 (2 m16 tiles) x 32 cols; K=128 in 4 chunks of 32
// staged via cp.async. Per k-step: 3 MMAs (xh*Wh, xh*Wl, xl*Wh), fp32 accum.

#define BB   50000
#define FF   128
#define EE   32
#define NNEG 10
#define ROWS 16
#define MV   416
#define NT   416
#define XSTR 36              // xs row stride (words): bank-safe + 16B mult
#define ESTR 34
#define TFMASK 0xFFFFE000u

struct SmemT {
    float whi[4096];         // W hi fragments, lane-major per (kstep,ntile)
    float wlo[4096];
    float bias[EE];
    float avec[2 * EE];
    float deltas[2];
    float sq[MV];
    float dots[ROWS * 6];
    float wts[ROWS * 4];
    alignas(16) union {
        float xs[MV * XSTR];     // 14976 floats: staging (k-chunk of 32)
        float emb[MV * ESTR];    // 14144 floats: epilogue
    } u;
};

#define MMA_TF32(d, a0, a1, a2, a3, b0, b1)                               \
    asm volatile("mma.sync.aligned.m16n8k8.row.col.f32.tf32.tf32.f32 "    \
        "{%0,%1,%2,%3}, {%4,%5,%6,%7}, {%8,%9}, {%0,%1,%2,%3};"           \
        : "+f"(d[0]), "+f"(d[1]), "+f"(d[2]), "+f"(d[3])                  \
        : "r"(a0), "r"(a1), "r"(a2), "r"(a3), "r"(b0), "r"(b1))

__device__ __forceinline__ int imin(int a, int b) { return a < b ? a : b; }

__device__ __forceinline__ void cp_async16(uint32_t smem_addr, const void* gptr) {
    asm volatile("cp.async.cg.shared.global [%0], [%1], 16;"
                 :: "r"(smem_addr), "l"(gptr) : "memory");
}

__global__ void __launch_bounds__(NT, 2) mmdne_kernel(
    const float* __restrict__ s_fts, const float* __restrict__ t_fts,
    const float* __restrict__ s_h_fts, const float* __restrict__ t_h_fts,
    const float* __restrict__ s_neg_fts, const float* __restrict__ t_neg_fts,
    const float* __restrict__ event_time,
    const float* __restrict__ s_h_times, const float* __restrict__ t_h_times,
    const float* __restrict__ s_h_mask, const float* __restrict__ t_h_mask,
    const float* __restrict__ W_fts, const float* __restrict__ b_fts,
    const float* __restrict__ a_vec,
    const float* __restrict__ delta_s, const float* __restrict__ delta_t,
    float* __restrict__ out)
{
    extern __shared__ char smem_raw[];
    SmemT& sm = *reinterpret_cast<SmemT*>(smem_raw);
    const int tid  = threadIdx.x;
    const int wid  = tid >> 5;
    const int lane = tid & 31;
    const int g    = lane >> 2;
    const int tg   = lane & 3;
    const int row_base = blockIdx.x * ROWS;

    // ---- Phase 0: params + W -> hi/lo tf32-split fragments ----
    if (tid < EE)     sm.bias[tid] = b_fts[tid];
    if (tid < 2 * EE) sm.avec[tid] = a_vec[tid];
    if (tid == 0) { sm.deltas[0] = delta_s[0]; sm.deltas[1] = delta_t[0]; }
    for (int idx = tid; idx < 4096; idx += NT) {
        int s   = idx >> 8;             // kstep 0..15
        int rem = idx & 255;
        int ntl = rem >> 6;             // ntile 0..3
        int l   = (rem >> 1) & 31;      // lane
        int wh  = idx & 1;
        int gg  = l >> 2, tt = l & 3;
        int k   = 8 * s + tt + (wh ? 4 : 0);
        int e   = 8 * ntl + gg;
        float w = W_fts[k * EE + e];
        uint32_t hb = __float_as_uint(w) & TFMASK;
        sm.whi[idx] = __uint_as_float(hb);
        sm.wlo[idx] = w - __uint_as_float(hb);
    }

    float acc[2][4][4];
#pragma unroll
    for (int mt = 0; mt < 2; ++mt)
#pragma unroll
        for (int nt = 0; nt < 4; ++nt)
#pragma unroll
            for (int j = 0; j < 4; ++j) acc[mt][nt][j] = 0.f;

    const uint32_t xs_base = (uint32_t)__cvta_generic_to_shared(sm.u.xs);

    // ---- K-chunk loop: cp.async 32 k-cols of all 416 rows, then MMA ----
    for (int c = 0; c < 4; ++c) {
        __syncthreads();   // xs free (prev chunk consumed / W frags written)
#pragma unroll
        for (int i = 0; i < 8; ++i) {
            int idx = tid + i * NT;            // 0..3327
            int m = idx >> 3;                  // vector-row 0..415
            int q = idx & 7;                   // float4 index within chunk
            const float* gp;
            if (m < 16)       gp = s_fts     + (long)imin(row_base + m,            BB - 1)      * FF;
            else if (m < 32)  gp = t_fts     + (long)imin(row_base + m - 16,       BB - 1)      * FF;
            else if (m < 64)  gp = s_h_fts   + (long)imin(row_base * 2 + m - 32,   2 * BB - 1)  * FF;
            else if (m < 96)  gp = t_h_fts   + (long)imin(row_base * 2 + m - 64,   2 * BB - 1)  * FF;
            else if (m < 256) gp = s_neg_fts + (long)imin(row_base * 10 + m - 96,  10 * BB - 1) * FF;
            else              gp = t_neg_fts + (long)imin(row_base * 10 + m - 256, 10 * BB - 1) * FF;
            cp_async16(xs_base + (uint32_t)((m * XSTR + 4 * q) * 4),
                       gp + 32 * c + 4 * q);
        }
        asm volatile("cp.async.commit_group;" ::: "memory");
        asm volatile("cp.async.wait_group 0;" ::: "memory");
        __syncthreads();

        const float* xw = sm.u.xs + (wid * 32) * XSTR;
#pragma unroll
        for (int kt = 0; kt < 4; ++kt) {
            const int sg = c * 4 + kt;
            uint32_t bh[4][2], bl[4][2];
#pragma unroll
            for (int nt = 0; nt < 4; ++nt) {
                float2 h  = *reinterpret_cast<const float2*>(&sm.whi[(sg * 4 + nt) * 64 + lane * 2]);
                float2 lo = *reinterpret_cast<const float2*>(&sm.wlo[(sg * 4 + nt) * 64 + lane * 2]);
                bh[nt][0] = __float_as_uint(h.x);  bh[nt][1] = __float_as_uint(h.y);
                bl[nt][0] = __float_as_uint(lo.x); bl[nt][1] = __float_as_uint(lo.y);
            }
#pragma unroll
            for (int mt = 0; mt < 2; ++mt) {
                const float* ap = xw + (16 * mt + g) * XSTR + 8 * kt + tg;
                float a0f = ap[0];
                float a1f = ap[8 * XSTR];
                float a2f = ap[4];
                float a3f = ap[8 * XSTR + 4];
                uint32_t ah0 = __float_as_uint(a0f) & TFMASK;
                uint32_t ah1 = __float_as_uint(a1f) & TFMASK;
                uint32_t ah2 = __float_as_uint(a2f) & TFMASK;
                uint32_t ah3 = __float_as_uint(a3f) & TFMASK;
                uint32_t al0 = __float_as_uint(a0f - __uint_as_float(ah0));
                uint32_t al1 = __float_as_uint(a1f - __uint_as_float(ah1));
                uint32_t al2 = __float_as_uint(a2f - __uint_as_float(ah2));
                uint32_t al3 = __float_as_uint(a3f - __uint_as_float(ah3));
#pragma unroll
                for (int nt = 0; nt < 4; ++nt) {
                    MMA_TF32(acc[mt][nt], ah0, ah1, ah2, ah3, bh[nt][0], bh[nt][1]);
                    MMA_TF32(acc[mt][nt], ah0, ah1, ah2, ah3, bl[nt][0], bl[nt][1]);
                    MMA_TF32(acc[mt][nt], al0, al1, al2, al3, bh[nt][0], bh[nt][1]);
                }
            }
        }
    }
    __syncthreads();   // xs consumed -> emb alias safe

    // ---- Epilogue A: bias add, emb stores, sqnorms, a-projections ----
#pragma unroll
    for (int mt = 0; mt < 2; ++mt) {
        const int r1 = wid * 32 + mt * 16 + g;
        const int r2 = r1 + 8;
        const float* av1 = sm.avec + ((r1 < 32) ? 0 : EE);
        const float* av2 = sm.avec + ((r2 < 32) ? 0 : EE);
        float s1 = 0.f, s2 = 0.f, d1 = 0.f, d2 = 0.f;
#pragma unroll
        for (int nt = 0; nt < 4; ++nt) {
            const int col = nt * 8 + tg * 2;
            float b0 = sm.bias[col], b1v = sm.bias[col + 1];
            float e0 = acc[mt][nt][0] + b0, e1 = acc[mt][nt][1] + b1v;
            float e2 = acc[mt][nt][2] + b0, e3 = acc[mt][nt][3] + b1v;
            *reinterpret_cast<float2*>(&sm.u.emb[r1 * ESTR + col]) = make_float2(e0, e1);
            *reinterpret_cast<float2*>(&sm.u.emb[r2 * ESTR + col]) = make_float2(e2, e3);
            s1 += e0 * e0 + e1 * e1;
            s2 += e2 * e2 + e3 * e3;
            d1 += e0 * av1[col] + e1 * av1[col + 1];
            d2 += e2 * av2[col] + e3 * av2[col + 1];
        }
        s1 += __shfl_xor_sync(0xFFFFFFFFu, s1, 1); s1 += __shfl_xor_sync(0xFFFFFFFFu, s1, 2);
        s2 += __shfl_xor_sync(0xFFFFFFFFu, s2, 1); s2 += __shfl_xor_sync(0xFFFFFFFFu, s2, 2);
        d1 += __shfl_xor_sync(0xFFFFFFFFu, d1, 1); d1 += __shfl_xor_sync(0xFFFFFFFFu, d1, 2);
        d2 += __shfl_xor_sync(0xFFFFFFFFu, d2, 1); d2 += __shfl_xor_sync(0xFFFFFFFFu, d2, 2);
        if (tg == 0) {
            sm.sq[r1] = s1;
            sm.sq[r2] = s2;
            // dots slots: s->0, t->1, s_h->2+h, t_h->4+h
            int mm = r1; float dd = d1;
#pragma unroll
            for (int rep = 0; rep < 2; ++rep) {
                if (mm < 16)      sm.dots[mm * 6 + 0] = dd;
                else if (mm < 32) sm.dots[(mm - 16) * 6 + 1] = dd;
                else if (mm < 64) sm.dots[((mm - 32) >> 1) * 6 + 2 + ((mm - 32) & 1)] = dd;
                else if (mm < 96) sm.dots[((mm - 64) >> 1) * 6 + 4 + ((mm - 64) & 1)] = dd;
                mm = r2; dd = d2;
            }
        }
    }
    __syncthreads();

    // ---- Epilogue B: per-row attention weights (16 threads) ----
    if (tid < ROWS) {
        const int r = tid;
        int rg = row_base + r; if (rg >= BB) rg = BB - 1;
        const float ds = sm.deltas[0];
        const float dt = sm.deltas[1];
        const float et = event_time[rg];

        float dts0 = fabsf(et - s_h_times[rg * 2 + 0]);
        float dts1 = fabsf(et - s_h_times[rg * 2 + 1]);
        float sc0 = sm.dots[r * 6 + 0] + sm.dots[r * 6 + 2];
        float sc1 = sm.dots[r * 6 + 0] + sm.dots[r * 6 + 3];
        float sim0 = expf(-ds * dts0) * sc0; sim0 = (sim0 > 0.f) ? sim0 : 0.2f * sim0;
        float sim1 = expf(-ds * dts1) * sc1; sim1 = (sim1 > 0.f) ? sim1 : 0.2f * sim1;
        float mx = fmaxf(sim0, sim1);
        float e0 = expf(sim0 - mx), e1 = expf(sim1 - mx);
        float inv = 1.f / (e0 + e1);
        sm.wts[r * 4 + 0] = e0 * inv * expf(ds * dts0) * s_h_mask[rg * 2 + 0];
        sm.wts[r * 4 + 1] = e1 * inv * expf(ds * dts1) * s_h_mask[rg * 2 + 1];

        float dtt0 = fabsf(et - t_h_times[rg * 2 + 0]);
        float dtt1 = fabsf(et - t_h_times[rg * 2 + 1]);
        float tc0 = sm.dots[r * 6 + 1] + sm.dots[r * 6 + 4];
        float tc1 = sm.dots[r * 6 + 1] + sm.dots[r * 6 + 5];
        float tm0 = expf(-dt * dtt0) * tc0; tm0 = (tm0 > 0.f) ? tm0 : 0.2f * tm0;
        float tm1 = expf(-dt * dtt1) * tc1; tm1 = (tm1 > 0.f) ? tm1 : 0.2f * tm1;
        float mx2 = fmaxf(tm0, tm1);
        float f0 = expf(tm0 - mx2), f1 = expf(tm1 - mx2);
        float inv2 = 1.f / (f0 + f1);
        sm.wts[r * 4 + 2] = f0 * inv2 * expf(dt * dtt0) * t_h_mask[rg * 2 + 0];
        sm.wts[r * 4 + 3] = f1 * inv2 * expf(dt * dtt1) * t_h_mask[rg * 2 + 1];
    }
    __syncthreads();

    // ---- Epilogue C: 21 outputs per row ----
    // Row map: s=r, t=16+r, s_h=32+2r+h, t_h=64+2r+h, s_n=96+10r+n, t_n=256+10r+n
    for (int it = tid; it < ROWS * 21; it += NT) {
        const int r = it / 21;
        const int k = it % 21;
        const int rg = row_base + r;
        if (rg >= BB) continue;
        const float* E = sm.u.emb;

        if (k == 0) {
            const float* es  = E + (r) * ESTR;
            const float* etb = E + (16 + r) * ESTR;
            const float* h0  = E + (32 + 2 * r) * ESTR;
            const float* h1  = E + (33 + 2 * r) * ESTR;
            float pm = 0.f, pa0 = 0.f, pa1 = 0.f;
#pragma unroll
            for (int e = 0; e < EE; ++e) {
                float te = etb[e];
                float d0 = es[e] - te; pm  -= d0 * d0;
                float d1 = h0[e] - te; pa0 -= d1 * d1;
                float d2 = h1[e] - te; pa1 -= d2 * d2;
            }
            out[rg] = pm + sm.wts[r * 4 + 0] * pa0 + sm.wts[r * 4 + 1] * pa1;
        } else if (k <= 10) {
            const int n = k - 1;
            const float* en = E + (256 + 10 * r + n) * ESTR;   // t_neg
            const float* es = E + (r) * ESTR;
            const float* h0 = E + (32 + 2 * r) * ESTR;
            const float* h1 = E + (33 + 2 * r) * ESTR;
            float d_s = 0.f, d0 = 0.f, d1 = 0.f;
#pragma unroll
            for (int e = 0; e < EE; ++e) {
                float x = en[e];
                d_s += es[e] * x;
                d0  += h0[e] * x;
                d1  += h1[e] * x;
            }
            float sqn = sm.sq[256 + 10 * r + n];
            float nmu = -(sm.sq[r] + sqn - 2.f * d_s);
            float na0 = -(sm.sq[32 + 2 * r] + sqn - 2.f * d0);
            float na1 = -(sm.sq[33 + 2 * r] + sqn - 2.f * d1);
            out[BB + (long)rg * NNEG + n] =
                nmu + sm.wts[r * 4 + 0] * na0 + sm.wts[r * 4 + 1] * na1;
        } else {
            const int n = k - 11;
            const float* en  = E + (96 + 10 * r + n) * ESTR;   // s_neg
            const float* et2 = E + (16 + r) * ESTR;
            const float* h0  = E + (64 + 2 * r) * ESTR;
            const float* h1  = E + (65 + 2 * r) * ESTR;
            float d_t = 0.f, d0 = 0.f, d1 = 0.f;
#pragma unroll
            for (int e = 0; e < EE; ++e) {
                float x = en[e];
                d_t += et2[e] * x;
                d0  += h0[e] * x;
                d1  += h1[e] * x;
            }
            float sqn = sm.sq[96 + 10 * r + n];
            float nmu = -(sm.sq[16 + r] + sqn - 2.f * d_t);
            float na0 = -(sm.sq[64 + 2 * r] + sqn - 2.f * d0);
            float na1 = -(sm.sq[65 + 2 * r] + sqn - 2.f * d1);
            out[BB + (long)BB * NNEG + (long)rg * NNEG + n] =
                nmu + sm.wts[r * 4 + 2] * na0 + sm.wts[r * 4 + 3] * na1;
        }
    }
}

extern "C" void kernel_launch(void* const* d_in, const int* in_sizes, int n_in,
                              void* d_out, int out_size)
{
    const float* s_fts      = (const float*)d_in[0];
    const float* t_fts      = (const float*)d_in[1];
    const float* s_h_fts    = (const float*)d_in[2];
    const float* t_h_fts    = (const float*)d_in[3];
    const float* s_neg_fts  = (const float*)d_in[4];
    const float* t_neg_fts  = (const float*)d_in[5];
    const float* event_time = (const float*)d_in[6];
    const float* s_h_times  = (const float*)d_in[7];
    const float* t_h_times  = (const float*)d_in[8];
    const float* s_h_mask   = (const float*)d_in[9];
    const float* t_h_mask   = (const float*)d_in[10];
    const float* W_fts      = (const float*)d_in[11];
    const float* b_fts      = (const float*)d_in[12];
    const float* a_vec      = (const float*)d_in[13];
    const float* delta_s    = (const float*)d_in[14];
    const float* delta_t    = (const float*)d_in[15];
    float* out = (float*)d_out;

    const int smem_bytes = (int)sizeof(SmemT);
    cudaFuncSetAttribute(mmdne_kernel,
                         cudaFuncAttributeMaxDynamicSharedMemorySize, smem_bytes);

    const int nblocks = BB / ROWS;   // 3125 exact
    mmdne_kernel<<<nblocks, NT, smem_bytes>>>(
        s_fts, t_fts, s_h_fts, t_h_fts, s_neg_fts, t_neg_fts,
        event_time, s_h_times, t_h_times, s_h_mask, t_h_mask,
        W_fts, b_fts, a_vec, delta_s, delta_t, out);
}